// round 3
// baseline (speedup 1.0000x reference)
#include <cuda_runtime.h>
#include <cstdint>
#include <cstddef>

// ---------------------------------------------------------------------------
// HoMESecondLayer fused kernel, fp32 SIMT, v2.
// ROWS 64 / 256 threads: TM=8 on the dominant 256x128 GEMM halves L1 weight
// traffic per FMA (the R1 limiter), register-double-buffered W prefetch.
// ---------------------------------------------------------------------------

constexpr int ROWS    = 64;
constexpr int THREADS = 256;
constexpr int META    = 128;
constexpr int GIN     = 256;

// Padded pitches (floats): multiples of 4 for float4, odd multiple of 4 to
// spread banks.
constexpr int CMP = 260;   // cm pitch (256 cols)
constexpr int AP  = 132;   // 128-col pitch
constexpr int BP  = 68;    // 64-col pitch

struct Smem {
    float cm [ROWS * CMP];   // gated concat(z_shared, z_group)   66560 B
    float a  [ROWS * AP];    // h1 / tower h1                     33792 B
    float b  [ROWS * BP];    // h2 / task-gate hidden             17408 B
    float c  [ROWS * BP];    // expert out e / tower h2           17408 B
    float agg[ROWS * BP];    // expert aggregation                17408 B
    float r  [ROWS * 8];     // low-rank gate intermediate
    float gw [ROWS * 4];     // softmax task-gate weights
    float lg [ROWS * 4];     // task-gate logits
};                           // ~153 KB -> 1 block / SM

__device__ __forceinline__ float sigm(float x)  { return 1.0f / (1.0f + __expf(-x)); }
__device__ __forceinline__ float swishf(float x){ return x   / (1.0f + __expf(-x)); }

// C[ROWS][N] = act( A[ROWS][K] @ W[K][N] + bias ).  A in smem, W in global.
// CT = N/4 column-threads; RG = THREADS/CT row groups; TM = ROWS/RG rows/thread.
// W double-buffered in registers: loads for chunk k+4 issue before FMAs of k.
template<int N, int K, int APITCH, int CPITCH, bool SW>
__device__ __forceinline__ void gemm_tile(const float* As,
                                          const float* __restrict__ Wg,
                                          const float* __restrict__ bg,
                                          float* Cs, int tid)
{
    constexpr int CT = N / 4;
    constexpr int RG = THREADS / CT;
    constexpr int TM = ROWS / RG;
    const int tc  = tid % CT;
    const int tr  = tid / CT;
    const int col = tc * 4;

    float acc[TM][4];
#pragma unroll
    for (int m = 0; m < TM; m++) {
        acc[m][0] = 0.f; acc[m][1] = 0.f; acc[m][2] = 0.f; acc[m][3] = 0.f;
    }

    float4 w[4];
#pragma unroll
    for (int kk = 0; kk < 4; kk++)
        w[kk] = __ldg(reinterpret_cast<const float4*>(Wg + (size_t)kk * N + col));

    for (int k = 0; k < K; k += 4) {
        float4 av[TM];
#pragma unroll
        for (int m = 0; m < TM; m++)
            av[m] = *reinterpret_cast<const float4*>(As + (tr * TM + m) * APITCH + k);

        // Prefetch next W chunk (redundant reload on the last iteration).
        const int kn = (k + 4 < K) ? (k + 4) : k;
        float4 wn[4];
#pragma unroll
        for (int kk = 0; kk < 4; kk++)
            wn[kk] = __ldg(reinterpret_cast<const float4*>(Wg + (size_t)(kn + kk) * N + col));

#pragma unroll
        for (int kk = 0; kk < 4; kk++) {
#pragma unroll
            for (int m = 0; m < TM; m++) {
                const float a = (kk == 0) ? av[m].x :
                                (kk == 1) ? av[m].y :
                                (kk == 2) ? av[m].z : av[m].w;
                acc[m][0] = fmaf(a, w[kk].x, acc[m][0]);
                acc[m][1] = fmaf(a, w[kk].y, acc[m][1]);
                acc[m][2] = fmaf(a, w[kk].z, acc[m][2]);
                acc[m][3] = fmaf(a, w[kk].w, acc[m][3]);
            }
        }
#pragma unroll
        for (int kk = 0; kk < 4; kk++) w[kk] = wn[kk];
    }

    const float4 bv = __ldg(reinterpret_cast<const float4*>(bg + col));
#pragma unroll
    for (int m = 0; m < TM; m++) {
        float r0 = acc[m][0] + bv.x;
        float r1 = acc[m][1] + bv.y;
        float r2 = acc[m][2] + bv.z;
        float r3 = acc[m][3] + bv.w;
        if (SW) { r0 = swishf(r0); r1 = swishf(r1); r2 = swishf(r2); r3 = swishf(r3); }
        float* cp = Cs + (tr * TM + m) * CPITCH + col;
        cp[0] = r0; cp[1] = r1; cp[2] = r2; cp[3] = r3;
    }
}

__global__ __launch_bounds__(THREADS, 1)
void home_kernel(
    const float* __restrict__ z_shared, const float* __restrict__ z_g0,
    const float* __restrict__ z_g1,
    const float* __restrict__ exp_W1, const float* __restrict__ exp_b1,
    const float* __restrict__ exp_W2, const float* __restrict__ exp_b2,
    const float* __restrict__ exp_W3, const float* __restrict__ exp_b3,
    const float* __restrict__ ln_s,   const float* __restrict__ ln_b,
    const float* __restrict__ fg_A,   const float* __restrict__ fg_B,
    const float* __restrict__ tg_W1,  const float* __restrict__ tg_b1,
    const float* __restrict__ tg_W2,  const float* __restrict__ tg_b2,
    const float* __restrict__ sg_W,   const float* __restrict__ sg_b,
    const float* __restrict__ tw_W1,  const float* __restrict__ tw_b1,
    const float* __restrict__ tw_W2,  const float* __restrict__ tw_b2,
    const float* __restrict__ tw_W3,  const float* __restrict__ tw_b3,
    float* __restrict__ out)
{
    extern __shared__ char smem_raw[];
    Smem& s = *reinterpret_cast<Smem*>(smem_raw);

    const int tid  = threadIdx.x;
    const int t    = blockIdx.y;          // task
    const int row0 = blockIdx.x * ROWS;
    const int g    = t >> 1;              // TASK_TO_GROUP = {0,0,1,1}
    const float* zg = g ? z_g1 : z_g0;

    // ---- 1. Load cm = concat(z_shared, z_group[g]) -----------------------
    for (int idx = tid; idx < ROWS * GIN / 4; idx += THREADS) {
        const int row = idx >> 6;       // 64 float4 per row
        const int k   = (idx & 63) * 4;
        float4 v;
        if (k < META)
            v = *reinterpret_cast<const float4*>(z_shared + (size_t)(row0 + row) * META + k);
        else
            v = *reinterpret_cast<const float4*>(zg + (size_t)(row0 + row) * META + (k - META));
        *reinterpret_cast<float4*>(&s.cm[row * CMP + k]) = v;
    }
    __syncthreads();

    // ---- 2a. r = cm @ fg_A[t]  (ROWS x 8) --------------------------------
    {
        const float* A = fg_A + (size_t)t * GIN * 8;
        for (int o = tid; o < ROWS * 8; o += THREADS) {
            const int row = o >> 3, j = o & 7;
            const float* cmr = &s.cm[row * CMP];
            float acc = 0.f;
#pragma unroll 4
            for (int k = 0; k < GIN; k++)
                acc = fmaf(cmr[k], __ldg(&A[k * 8 + j]), acc);
            s.r[row * 8 + j] = acc;
        }
    }
    __syncthreads();

    // ---- 2b. cm *= 2*sigmoid(r @ fg_B[t]) --------------------------------
    {
        const float* Bm = fg_B + (size_t)t * 8 * GIN;
        for (int idx = tid; idx < ROWS * GIN; idx += THREADS) {
            const int row = idx >> 8, k = idx & 255;
            const float* rr = &s.r[row * 8];
            float acc = 0.f;
#pragma unroll
            for (int j = 0; j < 8; j++)
                acc = fmaf(rr[j], __ldg(&Bm[j * GIN + k]), acc);
            s.cm[row * CMP + k] *= 2.0f * sigm(acc);
        }
    }
    __syncthreads();

    // ---- 3. Task gate ----------------------------------------------------
    gemm_tile<64, 256, CMP, BP, true>(s.cm, tg_W1 + (size_t)t * GIN * 64,
                                      tg_b1 + t * 64, s.b, tid);
    __syncthreads();
    {   // logits: 64 rows x 4 = 256 outputs = one per thread
        const int row = tid >> 2, j = tid & 3;
        const float* W  = tg_W2 + (size_t)t * 64 * 4;
        const float* gh = &s.b[row * BP];
        float acc = __ldg(&tg_b2[t * 4 + j]);
#pragma unroll 4
        for (int c = 0; c < 64; c++)
            acc = fmaf(gh[c], __ldg(&W[c * 4 + j]), acc);
        s.lg[row * 4 + j] = acc;
    }
    __syncthreads();
    if (tid < ROWS) {
        const float l0 = s.lg[tid * 4 + 0], l1 = s.lg[tid * 4 + 1];
        const float l2 = s.lg[tid * 4 + 2], l3 = s.lg[tid * 4 + 3];
        const float m  = fmaxf(fmaxf(l0, l1), fmaxf(l2, l3));
        const float e0 = __expf(l0 - m), e1 = __expf(l1 - m);
        const float e2 = __expf(l2 - m), e3 = __expf(l3 - m);
        const float inv = 1.0f / (e0 + e1 + e2 + e3);
        s.gw[tid * 4 + 0] = e0 * inv; s.gw[tid * 4 + 1] = e1 * inv;
        s.gw[tid * 4 + 2] = e2 * inv; s.gw[tid * 4 + 3] = e3 * inv;
    }
    __syncthreads();

    // ---- 4. Expert loop: eidx = {0, 1, 2+2g, 3+2g} -----------------------
    const int wid = tid >> 5, lane = tid & 31;
#pragma unroll 1
    for (int ep = 0; ep < 4; ep++) {
        const int e = (ep < 2) ? ep : (ep + 2 * g);

        gemm_tile<128, 256, CMP, AP, true >(s.cm, exp_W1 + (size_t)e * GIN * 128,
                                            exp_b1 + e * 128, s.a, tid);
        __syncthreads();
        gemm_tile<64, 128, AP, BP, true >(s.a,  exp_W2 + (size_t)e * 128 * 64,
                                          exp_b2 + e * 64, s.b, tid);
        __syncthreads();
        gemm_tile<64, 64,  BP, BP, false>(s.b,  exp_W3 + (size_t)e * 64 * 64,
                                          exp_b3 + e * 64, s.c, tid);
        __syncthreads();

        // LayerNorm + diag self-gate + softmax-weighted aggregation.
        // 8 warps, 8 rows each.
        {
            const float* lS  = ln_s + e * 64;
            const float* lB  = ln_b + e * 64;
            const float* sgw = sg_W + (size_t)t * 64 * 4;
            const float  sgb = __ldg(&sg_b[t * 4 + ep]);
#pragma unroll
            for (int rr = 0; rr < 8; rr++) {
                const int row = wid * 8 + rr;
                const float v0 = s.c[row * BP + lane];
                const float v1 = s.c[row * BP + lane + 32];
                float sum = v0 + v1;
                float sq  = fmaf(v0, v0, v1 * v1);
#pragma unroll
                for (int o = 16; o; o >>= 1) {
                    sum += __shfl_xor_sync(0xffffffffu, sum, o);
                    sq  += __shfl_xor_sync(0xffffffffu, sq,  o);
                }
                const float mu  = sum * (1.0f / 64.0f);
                const float var = sq * (1.0f / 64.0f) - mu * mu;
                const float inv = rsqrtf(var + 1e-5f);
                const float n0  = fmaf((v0 - mu) * inv, __ldg(&lS[lane]),      __ldg(&lB[lane]));
                const float n1  = fmaf((v1 - mu) * inv, __ldg(&lS[lane + 32]), __ldg(&lB[lane + 32]));
                float swp = fmaf(n0, __ldg(&sgw[lane * 4 + ep]),
                                 n1 * __ldg(&sgw[(lane + 32) * 4 + ep]));
#pragma unroll
                for (int o = 16; o; o >>= 1)
                    swp += __shfl_xor_sync(0xffffffffu, swp, o);
                const float scale = (swp + sgb) * s.gw[row * 4 + ep];
                if (ep == 0) {
                    s.agg[row * BP + lane]      = n0 * scale;
                    s.agg[row * BP + lane + 32] = n1 * scale;
                } else {
                    s.agg[row * BP + lane]      += n0 * scale;
                    s.agg[row * BP + lane + 32] += n1 * scale;
                }
            }
        }
        __syncthreads();
    }

    // ---- 5. Tower: agg -> 64 -> 32 -> 1 ----------------------------------
    gemm_tile<64, 64, BP, AP, true>(s.agg, tw_W1 + (size_t)t * 64 * 64,
                                    tw_b1 + t * 64, s.a, tid);
    __syncthreads();
    gemm_tile<32, 64, AP, BP, true>(s.a, tw_W2 + (size_t)t * 64 * 32,
                                    tw_b2 + t * 32, s.c, tid);
    __syncthreads();
    if (tid < ROWS) {
        const float* th = &s.c[tid * BP];
        const float* W  = tw_W3 + t * 32;
        float acc = __ldg(&tw_b3[t]);
#pragma unroll 4
        for (int c = 0; c < 32; c++)
            acc = fmaf(th[c], __ldg(&W[c]), acc);
        out[(size_t)(row0 + tid) * 4 + t] = sigm(acc);
    }
}

extern "C" void kernel_launch(void* const* d_in, const int* in_sizes, int n_in,
                              void* d_out, int out_size)
{
    (void)n_in; (void)out_size;
    const float* zs   = (const float*)d_in[0];
    const float* z0   = (const float*)d_in[1];
    const float* z1   = (const float*)d_in[2];
    // d_in[3] = v (unused by the reference computation)
    const float* eW1  = (const float*)d_in[4];
    const float* eb1  = (const float*)d_in[5];
    const float* eW2  = (const float*)d_in[6];
    const float* eb2  = (const float*)d_in[7];
    const float* eW3  = (const float*)d_in[8];
    const float* eb3  = (const float*)d_in[9];
    const float* lns  = (const float*)d_in[10];
    const float* lnb  = (const float*)d_in[11];
    const float* fgA  = (const float*)d_in[12];
    const float* fgB  = (const float*)d_in[13];
    const float* tgW1 = (const float*)d_in[14];
    const float* tgb1 = (const float*)d_in[15];
    const float* tgW2 = (const float*)d_in[16];
    const float* tgb2 = (const float*)d_in[17];
    const float* sgW  = (const float*)d_in[18];
    const float* sgb  = (const float*)d_in[19];
    const float* twW1 = (const float*)d_in[20];
    const float* twb1 = (const float*)d_in[21];
    const float* twW2 = (const float*)d_in[22];
    const float* twb2 = (const float*)d_in[23];
    const float* twW3 = (const float*)d_in[24];
    const float* twb3 = (const float*)d_in[25];

    const int Bn = in_sizes[0] / META;

    cudaFuncSetAttribute(home_kernel, cudaFuncAttributeMaxDynamicSharedMemorySize,
                         (int)sizeof(Smem));

    dim3 grid(Bn / ROWS, 4);
    home_kernel<<<grid, THREADS, sizeof(Smem)>>>(
        zs, z0, z1, eW1, eb1, eW2, eb2, eW3, eb3, lns, lnb,
        fgA, fgB, tgW1, tgb1, tgW2, tgb2, sgW, sgb,
        twW1, twb1, twW2, twb2, twW3, twb3, (float*)d_out);
}

// round 5
// speedup vs baseline: 1.6749x; 1.6749x over previous
#include <cuda_runtime.h>
#include <cstdint>
#include <cstddef>

#define DINL __device__ __forceinline__

// ---------------------------------------------------------------------------
// HoMESecondLayer v5: fused block (64 rows x 1 task), big GEMMs on tensor
// cores via mma.sync.m16n8k8 tf32 (plain sm_100 target - no tcgen05).
// ---------------------------------------------------------------------------

constexpr int ROWS    = 64;
constexpr int THREADS = 256;
constexpr int META    = 128;
constexpr int GIN     = 256;

// smem pitches: all ≡ 4 (mod 32) floats -> A-fragment LDS bank = (4r+c), conflict-free
constexpr int CMP = 260;   // cm pitch (256 cols)
constexpr int AP  = 132;   // 128-col pitch
constexpr int BP  = 68;    // 64-col pitch
// weight stage pitch: N + 8  -> ≡ 8 (mod 32) -> B-fragment bank = (8k+n), conflict-free
constexpr int WSTMAX = 64 * (128 + 8);   // 64-K chunk of a 128-col weight

struct Smem {
    float cm [ROWS * CMP];   // 66560 B
    float wst[WSTMAX];       // 34816 B  weight chunk stage (tf32 bits)
    float a  [ROWS * AP];    // 33792 B
    float b  [ROWS * BP];    // 17408 B
    float c  [ROWS * BP];    // 17408 B
    float agg[ROWS * BP];    // 17408 B
    float r  [ROWS * 8];
    float gw [ROWS * 4];
    float lg [ROWS * 4];
};                            // ~191 KB -> 1 block/SM

DINL float sigm(float x)   { return 1.0f / (1.0f + __expf(-x)); }
DINL float swishf(float x) { return x   / (1.0f + __expf(-x)); }
DINL uint32_t tf32_bits(float x) {
    uint32_t u; asm("cvt.rna.tf32.f32 %0, %1;" : "=r"(u) : "f"(x)); return u;
}
DINL void mma8(float* d, const uint32_t* a, const uint32_t* b) {
    asm volatile(
        "mma.sync.aligned.m16n8k8.row.col.f32.tf32.tf32.f32 "
        "{%0,%1,%2,%3}, {%4,%5,%6,%7}, {%8,%9}, {%0,%1,%2,%3};"
        : "+f"(d[0]), "+f"(d[1]), "+f"(d[2]), "+f"(d[3])
        : "r"(a[0]), "r"(a[1]), "r"(a[2]), "r"(a[3]), "r"(b[0]), "r"(b[1]));
}

// C[64][N] = act( A[64][K] @ W[K][N] + bias ) via tf32 mma.sync.
// Warp grid: N>=128 -> 4 warps along N (32 cols each) x 2 along M (32 rows, 2 mtiles)
//            N==64  -> 2 warps along N (32 cols)       x 4 along M (16 rows, 1 mtile)
template<int N, int K, int APITCH, int CPITCH, bool SW>
DINL void gemm_mma(const float* As, const float* __restrict__ Wg,
                   const float* __restrict__ bg, float* Cs,
                   float* wst, int tid)
{
    constexpr int WP = N + 8;
    constexpr int WN = (N >= 128) ? 4 : 2;
    constexpr int MT = (N >= 128) ? 2 : 1;
    const int w    = tid >> 5, lane = tid & 31;
    const int col0 = (w % WN) * 32;
    const int mrow0 = (w / WN) * (MT * 16);
    const int r = lane >> 2, c = lane & 3;

    float acc[MT][4][4];
#pragma unroll
    for (int mt = 0; mt < MT; mt++)
#pragma unroll
        for (int nt = 0; nt < 4; nt++)
#pragma unroll
            for (int i = 0; i < 4; i++) acc[mt][nt][i] = 0.f;

#pragma unroll 1
    for (int kc = 0; kc < K; kc += 64) {
        __syncthreads();
        // stage 64-K weight chunk, converting to tf32 bit patterns
        for (int i = tid; i < 64 * N / 4; i += THREADS) {
            const int row = i / (N / 4), cf = (i % (N / 4)) * 4;
            const float4 v = __ldg(reinterpret_cast<const float4*>(
                Wg + (size_t)(kc + row) * N + cf));
            float* dp = wst + row * WP + cf;
            dp[0] = __uint_as_float(tf32_bits(v.x));
            dp[1] = __uint_as_float(tf32_bits(v.y));
            dp[2] = __uint_as_float(tf32_bits(v.z));
            dp[3] = __uint_as_float(tf32_bits(v.w));
        }
        __syncthreads();

#pragma unroll
        for (int ks = 0; ks < 8; ks++) {
            const int kk = kc + ks * 8;
            uint32_t af[MT][4];
#pragma unroll
            for (int mt = 0; mt < MT; mt++) {
                const int base = mrow0 + mt * 16;
                af[mt][0] = tf32_bits(As[(base + r)     * APITCH + kk + c]);
                af[mt][1] = tf32_bits(As[(base + r + 8) * APITCH + kk + c]);
                af[mt][2] = tf32_bits(As[(base + r)     * APITCH + kk + c + 4]);
                af[mt][3] = tf32_bits(As[(base + r + 8) * APITCH + kk + c + 4]);
            }
            uint32_t bf[4][2];
#pragma unroll
            for (int nt = 0; nt < 4; nt++) {
                const int n = col0 + nt * 8 + r;
                bf[nt][0] = __float_as_uint(wst[(ks * 8 + c)     * WP + n]);
                bf[nt][1] = __float_as_uint(wst[(ks * 8 + c + 4) * WP + n]);
            }
#pragma unroll
            for (int mt = 0; mt < MT; mt++)
#pragma unroll
                for (int nt = 0; nt < 4; nt++)
                    mma8(acc[mt][nt], af[mt], bf[nt]);
        }
    }

    // epilogue: bias (+swish), store fp32 to Cs
#pragma unroll
    for (int mt = 0; mt < MT; mt++) {
        const int row = mrow0 + mt * 16 + r;
#pragma unroll
        for (int nt = 0; nt < 4; nt++) {
            const int cn = col0 + nt * 8 + 2 * c;
            const float b0 = __ldg(&bg[cn]), b1 = __ldg(&bg[cn + 1]);
            float v0 = acc[mt][nt][0] + b0, v1 = acc[mt][nt][1] + b1;
            float v2 = acc[mt][nt][2] + b0, v3 = acc[mt][nt][3] + b1;
            if (SW) { v0 = swishf(v0); v1 = swishf(v1); v2 = swishf(v2); v3 = swishf(v3); }
            Cs[row * CPITCH + cn]           = v0;
            Cs[row * CPITCH + cn + 1]       = v1;
            Cs[(row + 8) * CPITCH + cn]     = v2;
            Cs[(row + 8) * CPITCH + cn + 1] = v3;
        }
    }
}

// small SIMT gemm for the N=32 tower layer
template<int N, int K, int APITCH, int CPITCH, bool SW>
DINL void gemm_tile(const float* As, const float* __restrict__ Wg,
                    const float* __restrict__ bg, float* Cs, int tid)
{
    constexpr int CT = N / 4;
    constexpr int RG = THREADS / CT;
    constexpr int TM = ROWS / RG;
    const int tc = tid % CT, tr = tid / CT;
    const int col = tc * 4;

    float acc[TM][4];
#pragma unroll
    for (int m = 0; m < TM; m++) {
        acc[m][0] = 0.f; acc[m][1] = 0.f; acc[m][2] = 0.f; acc[m][3] = 0.f;
    }
    for (int k = 0; k < K; k++) {
        const float4 wv = __ldg(reinterpret_cast<const float4*>(Wg + (size_t)k * N + col));
#pragma unroll
        for (int m = 0; m < TM; m++) {
            const float a = As[(tr * TM + m) * APITCH + k];
            acc[m][0] = fmaf(a, wv.x, acc[m][0]);
            acc[m][1] = fmaf(a, wv.y, acc[m][1]);
            acc[m][2] = fmaf(a, wv.z, acc[m][2]);
            acc[m][3] = fmaf(a, wv.w, acc[m][3]);
        }
    }
    const float4 bv = __ldg(reinterpret_cast<const float4*>(bg + col));
#pragma unroll
    for (int m = 0; m < TM; m++) {
        float r0 = acc[m][0] + bv.x, r1 = acc[m][1] + bv.y;
        float r2 = acc[m][2] + bv.z, r3 = acc[m][3] + bv.w;
        if (SW) { r0 = swishf(r0); r1 = swishf(r1); r2 = swishf(r2); r3 = swishf(r3); }
        float* cp = Cs + (tr * TM + m) * CPITCH + col;
        cp[0] = r0; cp[1] = r1; cp[2] = r2; cp[3] = r3;
    }
}

__global__ __launch_bounds__(THREADS, 1)
void home_kernel(
    const float* __restrict__ z_shared, const float* __restrict__ z_g0,
    const float* __restrict__ z_g1,
    const float* __restrict__ exp_W1, const float* __restrict__ exp_b1,
    const float* __restrict__ exp_W2, const float* __restrict__ exp_b2,
    const float* __restrict__ exp_W3, const float* __restrict__ exp_b3,
    const float* __restrict__ ln_s,   const float* __restrict__ ln_b,
    const float* __restrict__ fg_A,   const float* __restrict__ fg_B,
    const float* __restrict__ tg_W1,  const float* __restrict__ tg_b1,
    const float* __restrict__ tg_W2,  const float* __restrict__ tg_b2,
    const float* __restrict__ sg_W,   const float* __restrict__ sg_b,
    const float* __restrict__ tw_W1,  const float* __restrict__ tw_b1,
    const float* __restrict__ tw_W2,  const float* __restrict__ tw_b2,
    const float* __restrict__ tw_W3,  const float* __restrict__ tw_b3,
    float* __restrict__ out)
{
    extern __shared__ char smem_raw[];
    Smem& s = *reinterpret_cast<Smem*>(smem_raw);

    const int tid  = threadIdx.x;
    const int t    = blockIdx.y;
    const int row0 = blockIdx.x * ROWS;
    const int g    = t >> 1;              // TASK_TO_GROUP = {0,0,1,1}
    const float* zg = g ? z_g1 : z_g0;

    // ---- 1. cm = concat(z_shared, z_group[g]) ----------------------------
    for (int idx = tid; idx < ROWS * GIN / 4; idx += THREADS) {
        const int row = idx >> 6;
        const int k   = (idx & 63) * 4;
        float4 v;
        if (k < META)
            v = *reinterpret_cast<const float4*>(z_shared + (size_t)(row0 + row) * META + k);
        else
            v = *reinterpret_cast<const float4*>(zg + (size_t)(row0 + row) * META + (k - META));
        *reinterpret_cast<float4*>(&s.cm[row * CMP + k]) = v;
    }
    __syncthreads();

    // ---- 2a. r = cm @ fg_A[t] --------------------------------------------
    {
        const float* A = fg_A + (size_t)t * GIN * 8;
        for (int o = tid; o < ROWS * 8; o += THREADS) {
            const int row = o >> 3, j = o & 7;
            const float* cmr = &s.cm[row * CMP];
            float acc = 0.f;
#pragma unroll 4
            for (int k = 0; k < GIN; k++)
                acc = fmaf(cmr[k], __ldg(&A[k * 8 + j]), acc);
            s.r[row * 8 + j] = acc;
        }
    }
    __syncthreads();

    // ---- 2b. cm *= 2*sigmoid(r @ fg_B[t]) --------------------------------
    {
        const float* Bm = fg_B + (size_t)t * 8 * GIN;
        for (int idx = tid; idx < ROWS * GIN; idx += THREADS) {
            const int row = idx >> 8, k = idx & 255;
            const float* rr = &s.r[row * 8];
            float acc = 0.f;
#pragma unroll
            for (int j = 0; j < 8; j++)
                acc = fmaf(rr[j], __ldg(&Bm[j * GIN + k]), acc);
            s.cm[row * CMP + k] *= 2.0f * sigm(acc);
        }
    }
    __syncthreads();

    // ---- 3. Task gate (tensor) -------------------------------------------
    gemm_mma<64, 256, CMP, BP, true>(s.cm, tg_W1 + (size_t)t * GIN * 64,
                                     tg_b1 + t * 64, s.b, s.wst, tid);
    __syncthreads();
    {
        const int row = tid >> 2, j = tid & 3;
        const float* W  = tg_W2 + (size_t)t * 64 * 4;
        const float* gh = &s.b[row * BP];
        float acc = __ldg(&tg_b2[t * 4 + j]);
#pragma unroll 4
        for (int c2 = 0; c2 < 64; c2++)
            acc = fmaf(gh[c2], __ldg(&W[c2 * 4 + j]), acc);
        s.lg[row * 4 + j] = acc;
    }
    __syncthreads();
    if (tid < ROWS) {
        const float l0 = s.lg[tid * 4 + 0], l1 = s.lg[tid * 4 + 1];
        const float l2 = s.lg[tid * 4 + 2], l3 = s.lg[tid * 4 + 3];
        const float m  = fmaxf(fmaxf(l0, l1), fmaxf(l2, l3));
        const float e0 = __expf(l0 - m), e1 = __expf(l1 - m);
        const float e2 = __expf(l2 - m), e3 = __expf(l3 - m);
        const float inv = 1.0f / (e0 + e1 + e2 + e3);
        s.gw[tid * 4 + 0] = e0 * inv; s.gw[tid * 4 + 1] = e1 * inv;
        s.gw[tid * 4 + 2] = e2 * inv; s.gw[tid * 4 + 3] = e3 * inv;
    }
    __syncthreads();

    // ---- 4. Experts (tensor) ---------------------------------------------
    const int wid = tid >> 5, lane = tid & 31;
#pragma unroll 1
    for (int ep = 0; ep < 4; ep++) {
        const int e = (ep < 2) ? ep : (ep + 2 * g);

        gemm_mma<128, 256, CMP, AP, true >(s.cm, exp_W1 + (size_t)e * GIN * 128,
                                           exp_b1 + e * 128, s.a, s.wst, tid);
        __syncthreads();
        gemm_mma<64, 128, AP, BP, true >(s.a, exp_W2 + (size_t)e * 128 * 64,
                                         exp_b2 + e * 64, s.b, s.wst, tid);
        __syncthreads();
        gemm_mma<64, 64,  BP, BP, false>(s.b, exp_W3 + (size_t)e * 64 * 64,
                                         exp_b3 + e * 64, s.c, s.wst, tid);
        __syncthreads();

        // LN + diag self-gate + softmax-weighted aggregation (8 warps x 8 rows)
        {
            const float* lS  = ln_s + e * 64;
            const float* lB  = ln_b + e * 64;
            const float* sgw = sg_W + (size_t)t * 64 * 4;
            const float  sgb = __ldg(&sg_b[t * 4 + ep]);
#pragma unroll
            for (int rr = 0; rr < 8; rr++) {
                const int row = wid * 8 + rr;
                const float v0 = s.c[row * BP + lane];
                const float v1 = s.c[row * BP + lane + 32];
                float sum = v0 + v1;
                float sq  = fmaf(v0, v0, v1 * v1);
#pragma unroll
                for (int o = 16; o; o >>= 1) {
                    sum += __shfl_xor_sync(0xffffffffu, sum, o);
                    sq  += __shfl_xor_sync(0xffffffffu, sq,  o);
                }
                const float mu  = sum * (1.0f / 64.0f);
                const float var = sq * (1.0f / 64.0f) - mu * mu;
                const float inv = rsqrtf(var + 1e-5f);
                const float n0  = fmaf((v0 - mu) * inv, __ldg(&lS[lane]),      __ldg(&lB[lane]));
                const float n1  = fmaf((v1 - mu) * inv, __ldg(&lS[lane + 32]), __ldg(&lB[lane + 32]));
                float swp = fmaf(n0, __ldg(&sgw[lane * 4 + ep]),
                                 n1 * __ldg(&sgw[(lane + 32) * 4 + ep]));
#pragma unroll
                for (int o = 16; o; o >>= 1)
                    swp += __shfl_xor_sync(0xffffffffu, swp, o);
                const float scale = (swp + sgb) * s.gw[row * 4 + ep];
                if (ep == 0) {
                    s.agg[row * BP + lane]      = n0 * scale;
                    s.agg[row * BP + lane + 32] = n1 * scale;
                } else {
                    s.agg[row * BP + lane]      += n0 * scale;
                    s.agg[row * BP + lane + 32] += n1 * scale;
                }
            }
        }
        __syncthreads();
    }

    // ---- 5. Tower ---------------------------------------------------------
    gemm_mma<64, 64, BP, AP, true>(s.agg, tw_W1 + (size_t)t * 64 * 64,
                                   tw_b1 + t * 64, s.a, s.wst, tid);
    __syncthreads();
    gemm_tile<32, 64, AP, BP, true>(s.a, tw_W2 + (size_t)t * 64 * 32,
                                    tw_b2 + t * 32, s.c, tid);
    __syncthreads();
    if (tid < ROWS) {
        const float* th = &s.c[tid * BP];
        const float* W  = tw_W3 + t * 32;
        float acc = __ldg(&tw_b3[t]);
#pragma unroll 4
        for (int c2 = 0; c2 < 32; c2++)
            acc = fmaf(th[c2], __ldg(&W[c2]), acc);
        out[(size_t)(row0 + tid) * 4 + t] = sigm(acc);
    }
}

extern "C" void kernel_launch(void* const* d_in, const int* in_sizes, int n_in,
                              void* d_out, int out_size)
{
    (void)n_in; (void)out_size;
    const float* zs   = (const float*)d_in[0];
    const float* z0   = (const float*)d_in[1];
    const float* z1   = (const float*)d_in[2];
    const float* eW1  = (const float*)d_in[4];
    const float* eb1  = (const float*)d_in[5];
    const float* eW2  = (const float*)d_in[6];
    const float* eb2  = (const float*)d_in[7];
    const float* eW3  = (const float*)d_in[8];
    const float* eb3  = (const float*)d_in[9];
    const float* lns  = (const float*)d_in[10];
    const float* lnb  = (const float*)d_in[11];
    const float* fgA  = (const float*)d_in[12];
    const float* fgB  = (const float*)d_in[13];
    const float* tgW1 = (const float*)d_in[14];
    const float* tgb1 = (const float*)d_in[15];
    const float* tgW2 = (const float*)d_in[16];
    const float* tgb2 = (const float*)d_in[17];
    const float* sgW  = (const float*)d_in[18];
    const float* sgb  = (const float*)d_in[19];
    const float* twW1 = (const float*)d_in[20];
    const float* twb1 = (const float*)d_in[21];
    const float* twW2 = (const float*)d_in[22];
    const float* twb2 = (const float*)d_in[23];
    const float* twW3 = (const float*)d_in[24];
    const float* twb3 = (const float*)d_in[25];

    const int Bn = in_sizes[0] / META;

    cudaFuncSetAttribute(home_kernel, cudaFuncAttributeMaxDynamicSharedMemorySize,
                         (int)sizeof(Smem));
    dim3 grid(Bn / ROWS, 4);
    home_kernel<<<grid, THREADS, sizeof(Smem)>>>(
        zs, z0, z1, eW1, eb1, eW2, eb2, eW3, eb3, lns, lnb,
        fgA, fgB, tgW1, tgb1, tgW2, tgb2, sgW, sgb,
        twW1, twb1, twW2, twb2, twW3, twb3, (float*)d_out);
}

// round 6
// speedup vs baseline: 3.7762x; 2.2546x over previous
#include <cuda_runtime.h>
#include <cuda_bf16.h>
#include <cstdint>
#include <cstddef>

#define DINL __device__ __forceinline__

// ---------------------------------------------------------------------------
// HoMESecondLayer v6: fused block (64 rows x 1 task), bf16 mma.m16n8k16,
// prep-transposed weight images, register-prefetch staging, 2 CTAs/SM.
// ---------------------------------------------------------------------------

constexpr int ROWS    = 64;
constexpr int THREADS = 256;
constexpr int META    = 128;
constexpr int GIN     = 256;

// bf16 weight images: W^T as [N][K], row-major K-contiguous.
constexpr int IW1 = 0;                    // 6 x [128][256]
constexpr int IW2 = IW1 + 6 * 128 * 256;  // 6 x [64][128]
constexpr int IW3 = IW2 + 6 * 64 * 128;   // 6 x [64][64]
constexpr int ITG = IW3 + 6 * 64 * 64;    // 4 x [64][256]
constexpr int IT1 = ITG + 4 * 64 * 256;   // 4 x [64][64]
constexpr int ITOT = IT1 + 4 * 64 * 64;
__device__ __align__(16) __nv_bfloat16 g_wimg[ITOT];

// smem layout (byte offsets). Region [0,61952) is overlaid by cm_fp32 during
// the gating phase, then used as wst/a/b/cfp for the GEMM phase.
constexpr int OFF_WST = 0;        // uint4[128*9]          18432 B
constexpr int OFF_A   = 18432;    // bf16 words 64*68      17408 B
constexpr int OFF_B   = 35840;    // bf16 words 64*36       9216 B
constexpr int OFF_CFP = 45056;    // float 64*66           16896 B  (end 61952)
constexpr int OFF_CMF = 0;        // overlay: float 64*260 66560 B
constexpr int OFF_CMB = 66560;    // bf16 words 64*132     33792 B
constexpr int OFF_R   = 100352;   // float 64*8             2048 B
constexpr int OFF_GW  = 102400;   // float 64*4             1024 B
constexpr int OFF_LG  = 103424;   // float 64*4             1024 B
constexpr int SMEM_TOTAL = 104448;

// pitches (32-bit words for bf16 buffers, floats for fp32)
constexpr int P_CM  = 132;  // 264 bf16, ≡4 mod 32 words
constexpr int P_A   = 68;   // 136 bf16
constexpr int P_B   = 36;   // 72 bf16
constexpr int P_CF  = 66;   // floats
constexpr int CMF_P = 260;  // floats

DINL float sigm(float x)   { return 1.0f / (1.0f + __expf(-x)); }
DINL float swishf(float x) { return x   / (1.0f + __expf(-x)); }

DINL void mma16(float* d, const uint32_t* a, uint32_t b0, uint32_t b1) {
    asm volatile(
        "mma.sync.aligned.m16n8k16.row.col.f32.bf16.bf16.f32 "
        "{%0,%1,%2,%3},{%4,%5,%6,%7},{%8,%9},{%0,%1,%2,%3};"
        : "+f"(d[0]), "+f"(d[1]), "+f"(d[2]), "+f"(d[3])
        : "r"(a[0]), "r"(a[1]), "r"(a[2]), "r"(a[3]), "r"(b0), "r"(b1));
}
DINL uint32_t packbf(float lo, float hi) {
    __nv_bfloat162 p = __floats2bfloat162_rn(lo, hi);
    return *reinterpret_cast<uint32_t*>(&p);
}

// ---- prep: W[nmat][K][N] fp32 -> bf16 W^T image [nmat][N][K] --------------
__global__ void prep_kernel(const float* __restrict__ src, int dstOff,
                            int K, int N, int nmat)
{
    const int total = nmat * K * N;
    for (int idx = blockIdx.x * blockDim.x + threadIdx.x; idx < total;
         idx += gridDim.x * blockDim.x) {
        const int m   = idx / (K * N);
        const int rem = idx - m * (K * N);
        const int n   = rem / K;
        const int k   = rem - n * K;
        g_wimg[dstOff + idx] = __float2bfloat16(src[(size_t)m * K * N + k * N + n]);
    }
}

// ---------------------------------------------------------------------------
// C[64][N] = act(A[64][K] @ W[K][N] + bias), A bf16 in smem (word pitch AP2),
// W from bf16 [N][K] image staged per-64K-chunk into wst with reg prefetch.
// OUTBF: write packed bf16 pairs (word pitch CP), else fp32 (float pitch CP).
// ---------------------------------------------------------------------------
template<int N, int K, int AP2, bool SW, bool OUTBF, int CP>
DINL void gemm_mma(const uint32_t* As, const __nv_bfloat16* Wimg,
                   const float* __restrict__ bias, void* Cs,
                   char* smbase, int tid)
{
    constexpr int NCH = K / 64;
    constexpr int PF  = N / 32;          // uint4 per thread per chunk
    constexpr int WN  = (N >= 128) ? 4 : 2;
    constexpr int MT  = (N >= 128) ? 2 : 1;
    uint4* wst4 = reinterpret_cast<uint4*>(smbase + OFF_WST);
    const uint32_t* wstw = reinterpret_cast<const uint32_t*>(smbase + OFF_WST);
    const int w = tid >> 5, lane = tid & 31;
    const int col0  = (w % WN) * 32;
    const int mrow0 = (w / WN) * (MT * 16);
    const int r = lane >> 2, c = lane & 3;

    float acc[MT][4][4];
#pragma unroll
    for (int mt = 0; mt < MT; mt++)
#pragma unroll
        for (int nt = 0; nt < 4; nt++)
#pragma unroll
            for (int i = 0; i < 4; i++) acc[mt][nt][i] = 0.f;

    const uint4* gsrc = reinterpret_cast<const uint4*>(Wimg);
    uint4 pre[PF];
#pragma unroll
    for (int j = 0; j < PF; j++) {
        const int i = tid + j * THREADS;
        pre[j] = __ldg(&gsrc[(i >> 3) * (K / 8) + (i & 7)]);
    }

#pragma unroll
    for (int kc = 0; kc < NCH; kc++) {
        __syncthreads();
#pragma unroll
        for (int j = 0; j < PF; j++) {
            const int i = tid + j * THREADS;
            wst4[(i >> 3) * 9 + (i & 7)] = pre[j];
        }
        __syncthreads();
        if (kc + 1 < NCH) {
#pragma unroll
            for (int j = 0; j < PF; j++) {
                const int i = tid + j * THREADS;
                pre[j] = __ldg(&gsrc[(i >> 3) * (K / 8) + (kc + 1) * 8 + (i & 7)]);
            }
        }
#pragma unroll
        for (int ks = 0; ks < 4; ks++) {
            const int ka = (kc * 64 + ks * 16) >> 1;   // word offset in A
            uint32_t af[MT][4];
#pragma unroll
            for (int mt = 0; mt < MT; mt++) {
                const int row = mrow0 + mt * 16 + r;
                af[mt][0] = As[row * AP2 + ka + c];
                af[mt][1] = As[(row + 8) * AP2 + ka + c];
                af[mt][2] = As[row * AP2 + ka + c + 4];
                af[mt][3] = As[(row + 8) * AP2 + ka + c + 4];
            }
            const int kb = ks * 8;
#pragma unroll
            for (int nt = 0; nt < 4; nt++) {
                const int n = col0 + nt * 8 + r;
                const uint32_t b0 = wstw[n * 36 + kb + c];
                const uint32_t b1 = wstw[n * 36 + kb + c + 4];
#pragma unroll
                for (int mt = 0; mt < MT; mt++) mma16(acc[mt][nt], af[mt], b0, b1);
            }
        }
    }

#pragma unroll
    for (int mt = 0; mt < MT; mt++) {
        const int row = mrow0 + mt * 16 + r;
#pragma unroll
        for (int nt = 0; nt < 4; nt++) {
            const int cn = col0 + nt * 8 + 2 * c;
            const float b0 = __ldg(&bias[cn]), b1 = __ldg(&bias[cn + 1]);
            float v0 = acc[mt][nt][0] + b0, v1 = acc[mt][nt][1] + b1;
            float v2 = acc[mt][nt][2] + b0, v3 = acc[mt][nt][3] + b1;
            if (SW) { v0 = swishf(v0); v1 = swishf(v1); v2 = swishf(v2); v3 = swishf(v3); }
            if (OUTBF) {
                uint32_t* C = reinterpret_cast<uint32_t*>(Cs);
                C[row * CP + (cn >> 1)]       = packbf(v0, v1);
                C[(row + 8) * CP + (cn >> 1)] = packbf(v2, v3);
            } else {
                float* C = reinterpret_cast<float*>(Cs);
                C[row * CP + cn] = v0; C[row * CP + cn + 1] = v1;
                C[(row + 8) * CP + cn] = v2; C[(row + 8) * CP + cn + 1] = v3;
            }
        }
    }
}

// small SIMT gemm for tower layer 2 (N=32): A fp32 smem -> C fp32 smem
DINL void gemm_t2(const float* As, const float* __restrict__ Wg,
                  const float* __restrict__ bg, float* Cs, int tid)
{
    constexpr int CT = 8, TM = 2;     // 32/4 col-threads, 64/(256/8) rows/thread
    const int tc = tid % CT, tr = tid / CT;
    const int col = tc * 4;
    float acc[TM][4];
#pragma unroll
    for (int m = 0; m < TM; m++) {
        acc[m][0] = 0.f; acc[m][1] = 0.f; acc[m][2] = 0.f; acc[m][3] = 0.f;
    }
    for (int k = 0; k < 64; k++) {
        const float4 wv = __ldg(reinterpret_cast<const float4*>(Wg + (size_t)k * 32 + col));
#pragma unroll
        for (int m = 0; m < TM; m++) {
            const float a = As[(tr * TM + m) * P_CF + k];
            acc[m][0] = fmaf(a, wv.x, acc[m][0]);
            acc[m][1] = fmaf(a, wv.y, acc[m][1]);
            acc[m][2] = fmaf(a, wv.z, acc[m][2]);
            acc[m][3] = fmaf(a, wv.w, acc[m][3]);
        }
    }
    const float4 bv = __ldg(reinterpret_cast<const float4*>(bg + col));
#pragma unroll
    for (int m = 0; m < TM; m++) {
        float* cp = Cs + (tr * TM + m) * P_B + col;
        cp[0] = swishf(acc[m][0] + bv.x);
        cp[1] = swishf(acc[m][1] + bv.y);
        cp[2] = swishf(acc[m][2] + bv.z);
        cp[3] = swishf(acc[m][3] + bv.w);
    }
}

__global__ __launch_bounds__(THREADS, 2)
void home_kernel(
    const float* __restrict__ z_shared, const float* __restrict__ z_g0,
    const float* __restrict__ z_g1,
    const float* __restrict__ exp_b1, const float* __restrict__ exp_b2,
    const float* __restrict__ exp_b3,
    const float* __restrict__ ln_s,   const float* __restrict__ ln_b,
    const float* __restrict__ fg_A,   const float* __restrict__ fg_B,
    const float* __restrict__ tg_b1,
    const float* __restrict__ tg_W2,  const float* __restrict__ tg_b2,
    const float* __restrict__ sg_W,   const float* __restrict__ sg_b,
    const float* __restrict__ tw_b1,
    const float* __restrict__ tw_W2,  const float* __restrict__ tw_b2,
    const float* __restrict__ tw_W3,  const float* __restrict__ tw_b3,
    float* __restrict__ out)
{
    extern __shared__ char sm[];
    float*    cmf = reinterpret_cast<float*>(sm + OFF_CMF);
    uint32_t* cmw = reinterpret_cast<uint32_t*>(sm + OFF_CMB);
    uint32_t* aw  = reinterpret_cast<uint32_t*>(sm + OFF_A);
    uint32_t* bw  = reinterpret_cast<uint32_t*>(sm + OFF_B);
    float*    cfp = reinterpret_cast<float*>(sm + OFF_CFP);
    float*    rb  = reinterpret_cast<float*>(sm + OFF_R);
    float*    gwb = reinterpret_cast<float*>(sm + OFF_GW);
    float*    lgb = reinterpret_cast<float*>(sm + OFF_LG);
    float*    twh2 = reinterpret_cast<float*>(sm + OFF_B);   // reuse after agg

    const int tid  = threadIdx.x;
    const int wid  = tid >> 5, lane = tid & 31;
    const int t    = blockIdx.y;
    const int g    = t >> 1;                    // TASK_TO_GROUP = {0,0,1,1}
    const int row0 = blockIdx.x * ROWS;
    const float* zg = g ? z_g1 : z_g0;

    // ---- 1. cm fp32 -> cmf -----------------------------------------------
    for (int idx = tid; idx < ROWS * GIN / 4; idx += THREADS) {
        const int row = idx >> 6;
        const int k   = (idx & 63) * 4;
        float4 v;
        if (k < META)
            v = *reinterpret_cast<const float4*>(z_shared + (size_t)(row0 + row) * META + k);
        else
            v = *reinterpret_cast<const float4*>(zg + (size_t)(row0 + row) * META + (k - META));
        *reinterpret_cast<float4*>(&cmf[row * CMF_P + k]) = v;
    }
    __syncthreads();

    // ---- 2a. r = cm @ fg_A[t] --------------------------------------------
    {
        const float* A = fg_A + (size_t)t * GIN * 8;
        for (int o = tid; o < ROWS * 8; o += THREADS) {
            const int row = o >> 3, j = o & 7;
            const float* cmr = &cmf[row * CMF_P];
            float acc = 0.f;
#pragma unroll 4
            for (int k = 0; k < GIN; k++)
                acc = fmaf(cmr[k], __ldg(&A[k * 8 + j]), acc);
            rb[row * 8 + j] = acc;
        }
    }
    __syncthreads();

    // ---- 2b. gated cm -> packed bf16 cmw ---------------------------------
    {
        const float* Bm = fg_B + (size_t)t * 8 * GIN;
        for (int idx = tid; idx < ROWS * 128; idx += THREADS) {
            const int row = idx >> 7, kp = idx & 127;
            const int k0 = 2 * kp;
            float v0 = cmf[row * CMF_P + k0], v1 = cmf[row * CMF_P + k0 + 1];
            const float* rr = &rb[row * 8];
            float d0 = 0.f, d1 = 0.f;
#pragma unroll
            for (int j = 0; j < 8; j++) {
                d0 = fmaf(rr[j], __ldg(&Bm[j * GIN + k0]),     d0);
                d1 = fmaf(rr[j], __ldg(&Bm[j * GIN + k0 + 1]), d1);
            }
            v0 *= 2.0f * sigm(d0);
            v1 *= 2.0f * sigm(d1);
            cmw[row * P_CM + kp] = packbf(v0, v1);
        }
    }
    __syncthreads();   // cmf dead; GEMM region free

    // ---- 3. task gate -----------------------------------------------------
    gemm_mma<64, 256, P_CM, true, false, P_CF>(
        cmw, g_wimg + ITG + t * 16384, tg_b1 + t * 64, cfp, sm, tid);
    __syncthreads();
    {
        const int row = tid >> 2, j = tid & 3;
        const float* W = tg_W2 + (size_t)t * 64 * 4;
        float acc = __ldg(&tg_b2[t * 4 + j]);
#pragma unroll 4
        for (int c2 = 0; c2 < 64; c2++)
            acc = fmaf(cfp[row * P_CF + c2], __ldg(&W[c2 * 4 + j]), acc);
        lgb[row * 4 + j] = acc;
    }
    __syncthreads();
    if (tid < ROWS) {
        const float l0 = lgb[tid * 4 + 0], l1 = lgb[tid * 4 + 1];
        const float l2 = lgb[tid * 4 + 2], l3 = lgb[tid * 4 + 3];
        const float m  = fmaxf(fmaxf(l0, l1), fmaxf(l2, l3));
        const float e0 = __expf(l0 - m), e1 = __expf(l1 - m);
        const float e2 = __expf(l2 - m), e3 = __expf(l3 - m);
        const float inv = 1.0f / (e0 + e1 + e2 + e3);
        gwb[tid * 4 + 0] = e0 * inv; gwb[tid * 4 + 1] = e1 * inv;
        gwb[tid * 4 + 2] = e2 * inv; gwb[tid * 4 + 3] = e3 * inv;
    }
    __syncthreads();

    // ---- 4. experts; agg accumulated in registers ------------------------
    float ag0[8], ag1[8];
#pragma unroll 1
    for (int ep = 0; ep < 4; ep++) {
        const int e = (ep < 2) ? ep : (ep + 2 * g);

        gemm_mma<128, 256, P_CM, true, true, P_A>(
            cmw, g_wimg + IW1 + e * 32768, exp_b1 + e * 128, aw, sm, tid);
        gemm_mma<64, 128, P_A, true, true, P_B>(
            aw, g_wimg + IW2 + e * 8192, exp_b2 + e * 64, bw, sm, tid);
        gemm_mma<64, 64, P_B, false, false, P_CF>(
            bw, g_wimg + IW3 + e * 4096, exp_b3 + e * 64, cfp, sm, tid);
        __syncthreads();

        // LN + diag self-gate + softmax aggregation: lane owns cols 2l,2l+1
        {
            const float* lS  = ln_s + e * 64;
            const float* lB  = ln_b + e * 64;
            const float* sgw = sg_W + (size_t)t * 256;
            const float  sgb = __ldg(&sg_b[t * 4 + ep]);
            const int c0 = 2 * lane, c1 = 2 * lane + 1;
#pragma unroll
            for (int rr = 0; rr < 8; rr++) {
                const int row = wid * 8 + rr;
                const float2 v = *reinterpret_cast<const float2*>(&cfp[row * P_CF + c0]);
                float sum = v.x + v.y;
                float sq  = fmaf(v.x, v.x, v.y * v.y);
#pragma unroll
                for (int o = 16; o; o >>= 1) {
                    sum += __shfl_xor_sync(0xffffffffu, sum, o);
                    sq  += __shfl_xor_sync(0xffffffffu, sq,  o);
                }
                const float mu  = sum * (1.0f / 64.0f);
                const float var = sq * (1.0f / 64.0f) - mu * mu;
                const float inv = rsqrtf(var + 1e-5f);
                const float n0  = fmaf((v.x - mu) * inv, __ldg(&lS[c0]), __ldg(&lB[c0]));
                const float n1  = fmaf((v.y - mu) * inv, __ldg(&lS[c1]), __ldg(&lB[c1]));
                float swp = fmaf(n0, __ldg(&sgw[c0 * 4 + ep]),
                                 n1 * __ldg(&sgw[c1 * 4 + ep]));
#pragma unroll
                for (int o = 16; o; o >>= 1)
                    swp += __shfl_xor_sync(0xffffffffu, swp, o);
                const float scale = (swp + sgb) * gwb[row * 4 + ep];
                if (ep == 0) { ag0[rr] = n0 * scale;            ag1[rr] = n1 * scale; }
                else         { ag0[rr] = fmaf(n0, scale, ag0[rr]); ag1[rr] = fmaf(n1, scale, ag1[rr]); }
            }
        }
        __syncthreads();
    }

    // ---- agg -> bf16 bw ---------------------------------------------------
#pragma unroll
    for (int rr = 0; rr < 8; rr++) {
        const int row = wid * 8 + rr;
        bw[row * P_B + lane] = packbf(ag0[rr], ag1[rr]);
    }
    // gemm's internal first __syncthreads orders these writes before reads

    // ---- 5. tower ---------------------------------------------------------
    gemm_mma<64, 64, P_B, true, false, P_CF>(
        bw, g_wimg + IT1 + t * 4096, tw_b1 + t * 64, cfp, sm, tid);
    __syncthreads();
    gemm_t2(cfp, tw_W2 + (size_t)t * 64 * 32, tw_b2 + t * 32, twh2, tid);
    __syncthreads();
    if (tid < ROWS) {
        const float* th = &twh2[tid * P_B];
        const float* W  = tw_W3 + t * 32;
        float acc = __ldg(&tw_b3[t]);
#pragma unroll 4
        for (int c2 = 0; c2 < 32; c2++)
            acc = fmaf(th[c2], __ldg(&W[c2]), acc);
        out[(size_t)(row0 + tid) * 4 + t] = sigm(acc);
    }
}

extern "C" void kernel_launch(void* const* d_in, const int* in_sizes, int n_in,
                              void* d_out, int out_size)
{
    (void)n_in; (void)out_size;
    const float* zs   = (const float*)d_in[0];
    const float* z0   = (const float*)d_in[1];
    const float* z1   = (const float*)d_in[2];
    const float* eW1  = (const float*)d_in[4];
    const float* eb1  = (const float*)d_in[5];
    const float* eW2  = (const float*)d_in[6];
    const float* eb2  = (const float*)d_in[7];
    const float* eW3  = (const float*)d_in[8];
    const float* eb3  = (const float*)d_in[9];
    const float* lns  = (const float*)d_in[10];
    const float* lnb  = (const float*)d_in[11];
    const float* fgA  = (const float*)d_in[12];
    const float* fgB  = (const float*)d_in[13];
    const float* tgW1 = (const float*)d_in[14];
    const float* tgb1 = (const float*)d_in[15];
    const float* tgW2 = (const float*)d_in[16];
    const float* tgb2 = (const float*)d_in[17];
    const float* sgW  = (const float*)d_in[18];
    const float* sgb  = (const float*)d_in[19];
    const float* twW1 = (const float*)d_in[20];
    const float* twb1 = (const float*)d_in[21];
    const float* twW2 = (const float*)d_in[22];
    const float* twb2 = (const float*)d_in[23];
    const float* twW3 = (const float*)d_in[24];
    const float* twb3 = (const float*)d_in[25];

    const int Bn = in_sizes[0] / META;

    prep_kernel<<<148, 256>>>(eW1,  IW1, 256, 128, 6);
    prep_kernel<<<148, 256>>>(eW2,  IW2, 128,  64, 6);
    prep_kernel<<<148, 256>>>(eW3,  IW3,  64,  64, 6);
    prep_kernel<<<148, 256>>>(tgW1, ITG, 256,  64, 4);
    prep_kernel<<<148, 256>>>(twW1, IT1,  64,  64, 4);

    cudaFuncSetAttribute(home_kernel, cudaFuncAttributeMaxDynamicSharedMemorySize,
                         SMEM_TOTAL);
    dim3 grid(Bn / ROWS, 4);
    home_kernel<<<grid, THREADS, SMEM_TOTAL>>>(
        zs, z0, z1, eb1, eb2, eb3, lns, lnb, fgA, fgB,
        tgb1, tgW2, tgb2, sgW, sgb, twb1, twW2, twb2, twW3, twb3,
        (float*)d_out);
}

// round 7
// speedup vs baseline: 4.7019x; 1.2451x over previous
#include <cuda_runtime.h>
#include <cuda_bf16.h>
#include <cstdint>
#include <cstddef>

#define DINL __device__ __forceinline__

// ---------------------------------------------------------------------------
// HoMESecondLayer v7: bf16 mma.m16n8k16 + ldmatrix fragment loads,
// smem-staged gating (no scalar-LDG storm), 2 CTAs/SM.
// ---------------------------------------------------------------------------

constexpr int ROWS    = 64;
constexpr int THREADS = 256;
constexpr int META    = 128;
constexpr int GIN     = 256;

// bf16 weight images: W^T as [N][K], row-major K-contiguous.
constexpr int IW1 = 0;                    // 6 x [128][256]
constexpr int IW2 = IW1 + 6 * 128 * 256;  // 6 x [64][128]
constexpr int IW3 = IW2 + 6 * 64 * 128;   // 6 x [64][64]
constexpr int ITG = IW3 + 6 * 64 * 64;    // 4 x [64][256]
constexpr int IT1 = ITG + 4 * 64 * 256;   // 4 x [64][64]
constexpr int ITOT = IT1 + 4 * 64 * 64;
__device__ __align__(16) __nv_bfloat16 g_wimg[ITOT];

// smem layout (byte offsets)
constexpr int OFF_WST = 0;        // uint4[128*9] 18432 B (gating: fgA+fgB 16KB)
constexpr int OFF_A   = 18432;    // bf16 words 64*68 = 17408 B (gating: slab 64*36 f)
constexpr int OFF_B   = 35840;    // bf16 words 64*36 = 9216 B
constexpr int OFF_CFP = 45056;    // float 64*66 = 16896 B
constexpr int OFF_CMB = 61952;    // bf16 words 64*132 = 33792 B
constexpr int OFF_R   = 95744;    // float 64*8
constexpr int OFF_GW  = 97792;    // float 64*4
constexpr int OFF_LG  = 98816;    // float 64*4
constexpr int SMEM_TOTAL = 99840;

// pitches (32-bit words for bf16 buffers, floats for fp32)
constexpr int P_CM = 132;  // (132/4)%8... 132 words = 33*16B, 33%8=1: LDSM-clean
constexpr int P_A  = 68;   // 17*16B
constexpr int P_B  = 36;   // 9*16B
constexpr int P_CF = 66;   // floats
constexpr int P_SL = 36;   // slab pitch (floats)

DINL float sigm(float x)   { return 1.0f / (1.0f + __expf(-x)); }
DINL float swishf(float x) { return x   / (1.0f + __expf(-x)); }
DINL uint32_t sm_addr(const void* p) {
    return (uint32_t)__cvta_generic_to_shared(p);
}
DINL void mma16(float* d, const uint32_t* a, uint32_t b0, uint32_t b1) {
    asm volatile(
        "mma.sync.aligned.m16n8k16.row.col.f32.bf16.bf16.f32 "
        "{%0,%1,%2,%3},{%4,%5,%6,%7},{%8,%9},{%0,%1,%2,%3};"
        : "+f"(d[0]), "+f"(d[1]), "+f"(d[2]), "+f"(d[3])
        : "r"(a[0]), "r"(a[1]), "r"(a[2]), "r"(a[3]), "r"(b0), "r"(b1));
}
DINL void ldsm4(uint32_t& r0, uint32_t& r1, uint32_t& r2, uint32_t& r3,
                uint32_t addr) {
    asm volatile(
        "ldmatrix.sync.aligned.m8n8.x4.shared.b16 {%0,%1,%2,%3}, [%4];"
        : "=r"(r0), "=r"(r1), "=r"(r2), "=r"(r3) : "r"(addr));
}
DINL uint32_t packbf(float lo, float hi) {
    __nv_bfloat162 p = __floats2bfloat162_rn(lo, hi);
    return *reinterpret_cast<uint32_t*>(&p);
}

// ---- prep: W[nmat][K][N] fp32 -> bf16 W^T image [nmat][N][K] --------------
__global__ void prep_kernel(const float* __restrict__ src, int dstOff,
                            int K, int N, int nmat)
{
    const int total = nmat * K * N;
    for (int idx = blockIdx.x * blockDim.x + threadIdx.x; idx < total;
         idx += gridDim.x * blockDim.x) {
        const int m   = idx / (K * N);
        const int rem = idx - m * (K * N);
        const int n   = rem / K;
        const int k   = rem - n * K;
        g_wimg[dstOff + idx] = __float2bfloat16(src[(size_t)m * K * N + k * N + n]);
    }
}

// ---------------------------------------------------------------------------
// C[64][N] = act(A[64][K] @ W[K][N] + bias). A bf16 in smem (word pitch AP2),
// W staged per-64K-chunk into wst (reg prefetch). All fragments via ldmatrix.
// ---------------------------------------------------------------------------
template<int N, int K, int AP2, bool SW, bool OUTBF, int CP>
DINL void gemm_mma(const uint32_t* As, const __nv_bfloat16* Wimg,
                   const float* __restrict__ bias, void* Cs,
                   char* smbase, int tid)
{
    constexpr int NCH = K / 64;
    constexpr int PF  = N / 32;
    constexpr int WN  = (N >= 128) ? 4 : 2;
    constexpr int MT  = (N >= 128) ? 2 : 1;
    uint4* wst4 = reinterpret_cast<uint4*>(smbase + OFF_WST);
    const int w = tid >> 5, lane = tid & 31;
    const int col0  = (w % WN) * 32;
    const int mrow0 = (w / WN) * (MT * 16);
    const int lrow = lane & 7, lg8 = (lane >> 3) & 1, lg16 = lane >> 4;

    const uint32_t abase = sm_addr(As);
    const uint32_t wbase = sm_addr(smbase + OFF_WST);
    uint32_t a_addr[MT];
#pragma unroll
    for (int mt = 0; mt < MT; mt++)
        a_addr[mt] = abase +
            ((mrow0 + mt * 16 + lg8 * 8 + lrow) * AP2 + lg16 * 4) * 4;
    uint32_t b_addr[2];
#pragma unroll
    for (int p = 0; p < 2; p++)
        b_addr[p] = wbase +
            ((col0 + p * 16 + lg16 * 8 + lrow) * 36 + lg8 * 4) * 4;

    float acc[MT][4][4];
#pragma unroll
    for (int mt = 0; mt < MT; mt++)
#pragma unroll
        for (int nt = 0; nt < 4; nt++)
#pragma unroll
            for (int i = 0; i < 4; i++) acc[mt][nt][i] = 0.f;

    const uint4* gsrc = reinterpret_cast<const uint4*>(Wimg);
    uint4 pre[PF];
#pragma unroll
    for (int j = 0; j < PF; j++) {
        const int i = tid + j * THREADS;
        pre[j] = __ldg(&gsrc[(i >> 3) * (K / 8) + (i & 7)]);
    }

#pragma unroll
    for (int kc = 0; kc < NCH; kc++) {
        __syncthreads();
#pragma unroll
        for (int j = 0; j < PF; j++) {
            const int i = tid + j * THREADS;
            wst4[(i >> 3) * 9 + (i & 7)] = pre[j];
        }
        __syncthreads();
        if (kc + 1 < NCH) {
#pragma unroll
            for (int j = 0; j < PF; j++) {
                const int i = tid + j * THREADS;
                pre[j] = __ldg(&gsrc[(i >> 3) * (K / 8) + (kc + 1) * 8 + (i & 7)]);
            }
        }
#pragma unroll
        for (int ks = 0; ks < 4; ks++) {
            uint32_t af[MT][4];
#pragma unroll
            for (int mt = 0; mt < MT; mt++)
                ldsm4(af[mt][0], af[mt][1], af[mt][2], af[mt][3],
                      a_addr[mt] + (kc * 64 + ks * 16) * 2);
            uint32_t bf[4][2];
#pragma unroll
            for (int p = 0; p < 2; p++)
                ldsm4(bf[2 * p][0], bf[2 * p][1], bf[2 * p + 1][0], bf[2 * p + 1][1],
                      b_addr[p] + ks * 32);
#pragma unroll
            for (int nt = 0; nt < 4; nt++)
#pragma unroll
                for (int mt = 0; mt < MT; mt++)
                    mma16(acc[mt][nt], af[mt], bf[nt][0], bf[nt][1]);
        }
    }

    const int r = lane >> 2, c = lane & 3;
#pragma unroll
    for (int mt = 0; mt < MT; mt++) {
        const int row = mrow0 + mt * 16 + r;
#pragma unroll
        for (int nt = 0; nt < 4; nt++) {
            const int cn = col0 + nt * 8 + 2 * c;
            const float b0 = __ldg(&bias[cn]), b1 = __ldg(&bias[cn + 1]);
            float v0 = acc[mt][nt][0] + b0, v1 = acc[mt][nt][1] + b1;
            float v2 = acc[mt][nt][2] + b0, v3 = acc[mt][nt][3] + b1;
            if (SW) { v0 = swishf(v0); v1 = swishf(v1); v2 = swishf(v2); v3 = swishf(v3); }
            if (OUTBF) {
                uint32_t* C = reinterpret_cast<uint32_t*>(Cs);
                C[row * CP + (cn >> 1)]       = packbf(v0, v1);
                C[(row + 8) * CP + (cn >> 1)] = packbf(v2, v3);
            } else {
                float* C = reinterpret_cast<float*>(Cs);
                C[row * CP + cn] = v0; C[row * CP + cn + 1] = v1;
                C[(row + 8) * CP + cn] = v2; C[(row + 8) * CP + cn + 1] = v3;
            }
        }
    }
}

// small SIMT gemm for tower layer 2 (N=32)
DINL void gemm_t2(const float* As, const float* __restrict__ Wg,
                  const float* __restrict__ bg, float* Cs, int tid)
{
    constexpr int CT = 8, TM = 2;
    const int tc = tid % CT, tr = tid / CT;
    const int col = tc * 4;
    float acc[TM][4];
#pragma unroll
    for (int m = 0; m < TM; m++) {
        acc[m][0] = 0.f; acc[m][1] = 0.f; acc[m][2] = 0.f; acc[m][3] = 0.f;
    }
    for (int k = 0; k < 64; k++) {
        const float4 wv = __ldg(reinterpret_cast<const float4*>(Wg + (size_t)k * 32 + col));
#pragma unroll
        for (int m = 0; m < TM; m++) {
            const float a = As[(tr * TM + m) * P_CF + k];
            acc[m][0] = fmaf(a, wv.x, acc[m][0]);
            acc[m][1] = fmaf(a, wv.y, acc[m][1]);
            acc[m][2] = fmaf(a, wv.z, acc[m][2]);
            acc[m][3] = fmaf(a, wv.w, acc[m][3]);
        }
    }
    const float4 bv = __ldg(reinterpret_cast<const float4*>(bg + col));
#pragma unroll
    for (int m = 0; m < TM; m++) {
        float* cp = Cs + (tr * TM + m) * P_B + col;
        cp[0] = swishf(acc[m][0] + bv.x);
        cp[1] = swishf(acc[m][1] + bv.y);
        cp[2] = swishf(acc[m][2] + bv.z);
        cp[3] = swishf(acc[m][3] + bv.w);
    }
}

__global__ __launch_bounds__(THREADS, 2)
void home_kernel(
    const float* __restrict__ z_shared, const float* __restrict__ z_g0,
    const float* __restrict__ z_g1,
    const float* __restrict__ exp_b1, const float* __restrict__ exp_b2,
    const float* __restrict__ exp_b3,
    const float* __restrict__ ln_s,   const float* __restrict__ ln_b,
    const float* __restrict__ fg_A,   const float* __restrict__ fg_B,
    const float* __restrict__ tg_b1,
    const float* __restrict__ tg_W2,  const float* __restrict__ tg_b2,
    const float* __restrict__ sg_W,   const float* __restrict__ sg_b,
    const float* __restrict__ tw_b1,
    const float* __restrict__ tw_W2,  const float* __restrict__ tw_b2,
    const float* __restrict__ tw_W3,  const float* __restrict__ tw_b3,
    float* __restrict__ out)
{
    extern __shared__ char sm[];
    float*    fga  = reinterpret_cast<float*>(sm + OFF_WST);          // [256][8]
    float*    fgb  = reinterpret_cast<float*>(sm + OFF_WST + 8192);   // [8][256]
    float*    slab = reinterpret_cast<float*>(sm + OFF_A);            // [64][36]
    uint32_t* cmw  = reinterpret_cast<uint32_t*>(sm + OFF_CMB);
    uint32_t* aw   = reinterpret_cast<uint32_t*>(sm + OFF_A);
    uint32_t* bw   = reinterpret_cast<uint32_t*>(sm + OFF_B);
    float*    cfp  = reinterpret_cast<float*>(sm + OFF_CFP);
    float*    rb   = reinterpret_cast<float*>(sm + OFF_R);
    float*    gwb  = reinterpret_cast<float*>(sm + OFF_GW);
    float*    lgb  = reinterpret_cast<float*>(sm + OFF_LG);
    float*    twh2 = reinterpret_cast<float*>(sm + OFF_B);

    const int tid  = threadIdx.x;
    const int wid  = tid >> 5, lane = tid & 31;
    const int t    = blockIdx.y;
    const int g    = t >> 1;                    // TASK_TO_GROUP = {0,0,1,1}
    const int row0 = blockIdx.x * ROWS;
    const float* zg = g ? z_g1 : z_g0;

    // ---- stage fgA [256][8] and fgB [8][256] into smem -------------------
    {
        const float4* A4 = reinterpret_cast<const float4*>(fg_A + (size_t)t * 2048);
        const float4* B4 = reinterpret_cast<const float4*>(fg_B + (size_t)t * 2048);
        float4* fa4 = reinterpret_cast<float4*>(fga);
        float4* fb4 = reinterpret_cast<float4*>(fgb);
#pragma unroll
        for (int i = 0; i < 2; i++) {
            fa4[tid + i * THREADS] = __ldg(&A4[tid + i * THREADS]);
            fb4[tid + i * THREADS] = __ldg(&B4[tid + i * THREADS]);
        }
    }
    __syncthreads();

    // ---- pass 1: r = cm @ fgA, slab-staged 32-col chunks ------------------
    const int grow = tid >> 2;            // 0..63
    const int jp   = (tid & 3) * 2;       // 0,2,4,6
    float r0 = 0.f, r1 = 0.f;
#pragma unroll 1
    for (int ch = 0; ch < 8; ch++) {
        const float* zsrc = (ch < 4) ? z_shared : zg;
        const int    cb   = (ch & 3) * 32;
#pragma unroll
        for (int i = 0; i < 2; i++) {
            const int idx = tid + i * THREADS;
            const int row = idx >> 3, c4 = (idx & 7) * 4;
            const float4 v = *reinterpret_cast<const float4*>(
                zsrc + (size_t)(row0 + row) * META + cb + c4);
            *reinterpret_cast<float4*>(&slab[row * P_SL + c4]) = v;
        }
        __syncthreads();
#pragma unroll 8
        for (int k = 0; k < 32; k++) {
            const float a = slab[grow * P_SL + k];
            const float2 f = *reinterpret_cast<const float2*>(
                &fga[(ch * 32 + k) * 8 + jp]);
            r0 = fmaf(a, f.x, r0);
            r1 = fmaf(a, f.y, r1);
        }
        __syncthreads();
    }
    rb[grow * 8 + jp]     = r0;
    rb[grow * 8 + jp + 1] = r1;
    __syncthreads();

    // ---- pass 2: gate + pack bf16 cm --------------------------------------
#pragma unroll 1
    for (int ch = 0; ch < 8; ch++) {
        const float* zsrc = (ch < 4) ? z_shared : zg;
        const int    cb   = (ch & 3) * 32;
#pragma unroll
        for (int i = 0; i < 2; i++) {
            const int idx = tid + i * THREADS;
            const int row = idx >> 3, c4 = (idx & 7) * 4;
            const float4 v = *reinterpret_cast<const float4*>(
                zsrc + (size_t)(row0 + row) * META + cb + c4);
            *reinterpret_cast<float4*>(&slab[row * P_SL + c4]) = v;
        }
        __syncthreads();
#pragma unroll
        for (int i = 0; i < 4; i++) {
            const int p   = tid + i * THREADS;
            const int row = p >> 4, pp = p & 15;
            const float2 v = *reinterpret_cast<const float2*>(
                &slab[row * P_SL + 2 * pp]);
            const float* rr = &rb[row * 8];
            float d0 = 0.f, d1 = 0.f;
#pragma unroll
            for (int j = 0; j < 8; j++) {
                const float2 b = *reinterpret_cast<const float2*>(
                    &fgb[j * 256 + ch * 32 + 2 * pp]);
                d0 = fmaf(rr[j], b.x, d0);
                d1 = fmaf(rr[j], b.y, d1);
            }
            cmw[row * P_CM + ch * 16 + pp] =
                packbf(v.x * 2.0f * sigm(d0), v.y * 2.0f * sigm(d1));
        }
        __syncthreads();
    }

    // ---- 3. task gate ------------------------------------------------------
    gemm_mma<64, 256, P_CM, true, false, P_CF>(
        cmw, g_wimg + ITG + t * 16384, tg_b1 + t * 64, cfp, sm, tid);
    __syncthreads();
    {
        const int row = tid >> 2, j = tid & 3;
        const float* W = tg_W2 + (size_t)t * 64 * 4;
        float acc = __ldg(&tg_b2[t * 4 + j]);
#pragma unroll 4
        for (int c2 = 0; c2 < 64; c2++)
            acc = fmaf(cfp[row * P_CF + c2], __ldg(&W[c2 * 4 + j]), acc);
        lgb[row * 4 + j] = acc;
    }
    __syncthreads();
    if (tid < ROWS) {
        const float l0 = lgb[tid * 4 + 0], l1 = lgb[tid * 4 + 1];
        const float l2 = lgb[tid * 4 + 2], l3 = lgb[tid * 4 + 3];
        const float m  = fmaxf(fmaxf(l0, l1), fmaxf(l2, l3));
        const float e0 = __expf(l0 - m), e1 = __expf(l1 - m);
        const float e2 = __expf(l2 - m), e3 = __expf(l3 - m);
        const float inv = 1.0f / (e0 + e1 + e2 + e3);
        gwb[tid * 4 + 0] = e0 * inv; gwb[tid * 4 + 1] = e1 * inv;
        gwb[tid * 4 + 2] = e2 * inv; gwb[tid * 4 + 3] = e3 * inv;
    }
    __syncthreads();

    // ---- 4. experts --------------------------------------------------------
    float ag0[8], ag1[8];
#pragma unroll 1
    for (int ep = 0; ep < 4; ep++) {
        const int e = (ep < 2) ? ep : (ep + 2 * g);

        gemm_mma<128, 256, P_CM, true, true, P_A>(
            cmw, g_wimg + IW1 + e * 32768, exp_b1 + e * 128, aw, sm, tid);
        gemm_mma<64, 128, P_A, true, true, P_B>(
            aw, g_wimg + IW2 + e * 8192, exp_b2 + e * 64, bw, sm, tid);
        gemm_mma<64, 64, P_B, false, false, P_CF>(
            bw, g_wimg + IW3 + e * 4096, exp_b3 + e * 64, cfp, sm, tid);
        __syncthreads();

        {
            const float* lS  = ln_s + e * 64;
            const float* lB  = ln_b + e * 64;
            const float* sgw = sg_W + (size_t)t * 256;
            const float  sgb = __ldg(&sg_b[t * 4 + ep]);
            const int c0 = 2 * lane, c1 = 2 * lane + 1;
#pragma unroll
            for (int rr = 0; rr < 8; rr++) {
                const int row = wid * 8 + rr;
                const float2 v = *reinterpret_cast<const float2*>(&cfp[row * P_CF + c0]);
                float sum = v.x + v.y;
                float sq  = fmaf(v.x, v.x, v.y * v.y);
#pragma unroll
                for (int o = 16; o; o >>= 1) {
                    sum += __shfl_xor_sync(0xffffffffu, sum, o);
                    sq  += __shfl_xor_sync(0xffffffffu, sq,  o);
                }
                const float mu  = sum * (1.0f / 64.0f);
                const float var = sq * (1.0f / 64.0f) - mu * mu;
                const float inv = rsqrtf(var + 1e-5f);
                const float n0  = fmaf((v.x - mu) * inv, __ldg(&lS[c0]), __ldg(&lB[c0]));
                const float n1  = fmaf((v.y - mu) * inv, __ldg(&lS[c1]), __ldg(&lB[c1]));
                float swp = fmaf(n0, __ldg(&sgw[c0 * 4 + ep]),
                                 n1 * __ldg(&sgw[c1 * 4 + ep]));
#pragma unroll
                for (int o = 16; o; o >>= 1)
                    swp += __shfl_xor_sync(0xffffffffu, swp, o);
                const float scale = (swp + sgb) * gwb[row * 4 + ep];
                if (ep == 0) { ag0[rr] = n0 * scale;               ag1[rr] = n1 * scale; }
                else         { ag0[rr] = fmaf(n0, scale, ag0[rr]); ag1[rr] = fmaf(n1, scale, ag1[rr]); }
            }
        }
        __syncthreads();
    }

    // ---- agg -> bf16 bw ----------------------------------------------------
#pragma unroll
    for (int rr = 0; rr < 8; rr++) {
        const int row = wid * 8 + rr;
        bw[row * P_B + lane] = packbf(ag0[rr], ag1[rr]);
    }
    // gemm's leading __syncthreads orders these writes before fragment reads

    // ---- 5. tower ----------------------------------------------------------
    gemm_mma<64, 64, P_B, true, false, P_CF>(
        bw, g_wimg + IT1 + t * 4096, tw_b1 + t * 64, cfp, sm, tid);
    __syncthreads();
    gemm_t2(cfp, tw_W2 + (size_t)t * 64 * 32, tw_b2 + t * 32, twh2, tid);
    __syncthreads();
    if (tid < ROWS) {
        const float* th = &twh2[tid * P_B];
        const float* W  = tw_W3 + t * 32;
        float acc = __ldg(&tw_b3[t]);
#pragma unroll 4
        for (int c2 = 0; c2 < 32; c2++)
            acc = fmaf(th[c2], __ldg(&W[c2]), acc);
        out[(size_t)(row0 + tid) * 4 + t] = sigm(acc);
    }
}

extern "C" void kernel_launch(void* const* d_in, const int* in_sizes, int n_in,
                              void* d_out, int out_size)
{
    (void)n_in; (void)out_size;
    const float* zs   = (const float*)d_in[0];
    const float* z0   = (const float*)d_in[1];
    const float* z1   = (const float*)d_in[2];
    const float* eW1  = (const float*)d_in[4];
    const float* eb1  = (const float*)d_in[5];
    const float* eW2  = (const float*)d_in[6];
    const float* eb2  = (const float*)d_in[7];
    const float* eW3  = (const float*)d_in[8];
    const float* eb3  = (const float*)d_in[9];
    const float* lns  = (const float*)d_in[10];
    const float* lnb  = (const float*)d_in[11];
    const float* fgA  = (const float*)d_in[12];
    const float* fgB  = (const float*)d_in[13];
    const float* tgW1 = (const float*)d_in[14];
    const float* tgb1 = (const float*)d_in[15];
    const float* tgW2 = (const float*)d_in[16];
    const float* tgb2 = (const float*)d_in[17];
    const float* sgW  = (const float*)d_in[18];
    const float* sgb  = (const float*)d_in[19];
    const float* twW1 = (const float*)d_in[20];
    const float* twb1 = (const float*)d_in[21];
    const float* twW2 = (const float*)d_in[22];
    const float* twb2 = (const float*)d_in[23];
    const float* twW3 = (const float*)d_in[24];
    const float* twb3 = (const float*)d_in[25];

    const int Bn = in_sizes[0] / META;

    prep_kernel<<<148, 256>>>(eW1,  IW1, 256, 128, 6);
    prep_kernel<<<148, 256>>>(eW2,  IW2, 128,  64, 6);
    prep_kernel<<<148, 256>>>(eW3,  IW3,  64,  64, 6);
    prep_kernel<<<148, 256>>>(tgW1, ITG, 256,  64, 4);
    prep_kernel<<<148, 256>>>(twW1, IT1,  64,  64, 4);

    cudaFuncSetAttribute(home_kernel, cudaFuncAttributeMaxDynamicSharedMemorySize,
                         SMEM_TOTAL);
    dim3 grid(Bn / ROWS, 4);
    home_kernel<<<grid, THREADS, SMEM_TOTAL>>>(
        zs, z0, z1, eb1, eb2, eb3, lns, lnb, fgA, fgB,
        tgb1, tgW2, tgb2, sgW, sgb, twb1, twW2, twb2, twW3, twb3,
        (float*)d_out);
}